// round 12
// baseline (speedup 1.0000x reference)
#include <cuda_runtime.h>
#include <cuda_fp16.h>
#include <cstdint>

#define CIN   64
#define COUT  64
#define HH    224
#define WW    224
#define NB    16
#define WPAD  232      // padded w: index widx = w+1, w in [-1, 230]

// ---------------- smem layout (bytes) ----------------
#define A_OFF     0
#define A_ROWS    770
#define A_BYTES   (A_ROWS * 128)               // 98560
#define ALPHA_OFF (A_OFF + A_BYTES)
#define BIAS_OFF  (ALPHA_OFF + 256)
#define MB_OFF    (BIAS_OFF + 256)             // two mbarriers (8B each)
#define SMEM_TOTAL (MB_OFF + 64)               // 99136

// Plain ternary pattern [tap][co][ci] (fp16, exact)
__device__ __half g_plain[9 * COUT * CIN];
// Analytic mma B fragments: [tap][n8group(8)][kc(4)][lane(32)] x uint2
__device__ uint2 g_wfrag[9 * 8 * 4 * 32];
__device__ float g_alpha[COUT];
// x fp16, NHWC padded + octet-swizzled: [n][h][widx][64ci],
// octet o of ci stored at physical slot o ^ ((w+2)&7); widx = w+1.
__device__ __half g_xh[(size_t)NB * HH * WPAD * CIN];

// ---------------------------------------------------------------------------
// Kernel 1: ternarize -> fp16 {-1,0,+1} pattern + per-cout alpha
// ---------------------------------------------------------------------------
__global__ void ternarize_kernel(const float* __restrict__ w) {
    __shared__ float red[256];
    __shared__ float red2[256];
    const int co  = blockIdx.x;
    const int tid = threadIdx.x;
    const float* wf = w + co * 576;

    float s = 0.f;
    for (int i = tid; i < 576; i += 256) s += fabsf(wf[i]);
    red[tid] = s;
    __syncthreads();
    for (int o = 128; o > 0; o >>= 1) {
        if (tid < o) red[tid] += red[tid + o];
        __syncthreads();
    }
    const float delta = (0.7f / 576.f) * red[0];
    __syncthreads();

    float cnt = 0.f, ms = 0.f;
    for (int i = tid; i < 576; i += 256) {
        float a = fabsf(wf[i]);
        if (a > delta) { cnt += 1.f; ms += a; }
    }
    red[tid] = ms; red2[tid] = cnt;
    __syncthreads();
    for (int o = 128; o > 0; o >>= 1) {
        if (tid < o) { red[tid] += red[tid + o]; red2[tid] += red2[tid + o]; }
        __syncthreads();
    }
    float count = (red2[0] == 0.f) ? 1.f : red2[0];
    float alpha = fmaxf(red[0] / count, 1e-4f);
    if (tid == 0) g_alpha[co] = alpha;

    for (int i = tid; i < 576; i += 256) {
        int ci  = i / 9;
        int tap = i - ci * 9;
        float v = wf[i];
        float t = (v > delta) ? 1.f : ((v < -delta) ? -1.f : 0.f);
        g_plain[tap * 4096 + co * 64 + ci] = __float2half_rn(t);
    }
}

// ---------------------------------------------------------------------------
// Kernel 1b: pack B fragments in mma.m16n8k16 per-lane layout.
// ---------------------------------------------------------------------------
__global__ void pack_wfrag_kernel() {
    int tid = blockIdx.x * 256 + threadIdx.x;
    if (tid >= 9 * 8 * 4 * 32) return;
    int lane = tid & 31;
    int kc   = (tid >> 5) & 3;
    int g    = (tid >> 7) & 7;
    int tap  = tid >> 10;

    int co = g * 8 + (lane >> 2);
    int k0 = kc * 16 + 2 * (lane & 3);
    const __half* p = g_plain + tap * 4096 + co * 64;

    __half2 w0 = __halves2half2(p[k0],     p[k0 + 1]);
    __half2 w1 = __halves2half2(p[k0 + 8], p[k0 + 9]);
    uint2 v;
    v.x = *(const uint32_t*)&w0;
    v.y = *(const uint32_t*)&w1;
    g_wfrag[((tap * 8 + g) * 4 + kc) * 32 + lane] = v;
}

// ---------------------------------------------------------------------------
// Kernel 1c: x fp32 NCHW -> fp16 NHWC (padded, octet-swizzled).
// Block = one (n, h). Tasks = (w-quad, octet): 56*8 = 448.
// Each task: 8 LDG.128 (8 ci, 4 w) -> 4 STS.128 (swizzled). Then linear
// LDS.128 -> STG.128 copy-out (smem layout == global layout).
// ---------------------------------------------------------------------------
__global__ __launch_bounds__(256)
void transform_kernel(const float* __restrict__ x) {
    __shared__ uint4 tile[224 * 8];
    const int h = blockIdx.x;
    const int n = blockIdx.y;
    const int tid = threadIdx.x;

    for (int i = tid; i < 448; i += 256) {
        int q = i % 56;          // w-quad
        int o = i / 56;          // octet (8 ci)
        float4 f[8];
        #pragma unroll
        for (int k = 0; k < 8; k++)
            f[k] = *(const float4*)(x + ((size_t)(n * 64 + o * 8 + k) * HH + h) * WW + q * 4);
        #pragma unroll
        for (int j = 0; j < 4; j++) {
            const float* fp = (const float*)f;   // f[k] component j = fp[k*4+j]
            uint32_t u[4];
            #pragma unroll
            for (int m = 0; m < 4; m++) {
                __half2 hv = __floats2half2_rn(fp[(2 * m) * 4 + j], fp[(2 * m + 1) * 4 + j]);
                u[m] = *(const uint32_t*)&hv;
            }
            int w    = q * 4 + j;
            int phys = o ^ ((w + 2) & 7);
            tile[w * 8 + phys] = make_uint4(u[0], u[1], u[2], u[3]);
        }
    }
    __syncthreads();

    __half* dst = g_xh + ((size_t)(n * HH + h) * WPAD + 1) * 64;
    for (int i = tid; i < 224 * 8; i += 256)
        *(uint4*)((char*)dst + (size_t)i * 16) = tile[i];

    // zero pads: widx 0 and 225..231
    if (tid < 64) {
        int idx  = tid >> 3;
        int u    = tid & 7;
        int widx = (idx == 0) ? 0 : (224 + idx);
        *(uint4*)(g_xh + ((size_t)(n * HH + h) * WPAD + widx) * 64 + u * 8) =
            make_uint4(0, 0, 0, 0);
    }
}

// ---------------------------------------------------------------------------
// Baseline-PTX helpers
// ---------------------------------------------------------------------------
__device__ __forceinline__ uint32_t smem_u32(const void* p) {
    uint32_t a;
    asm("{ .reg .u64 t; cvta.to.shared.u64 t, %1; cvt.u32.u64 %0, t; }" : "=r"(a) : "l"(p));
    return a;
}
__device__ __forceinline__ void ldsm_x4(uint32_t* r, uint32_t addr) {
    asm volatile("ldmatrix.sync.aligned.m8n8.x4.shared.b16 {%0,%1,%2,%3}, [%4];"
                 : "=r"(r[0]), "=r"(r[1]), "=r"(r[2]), "=r"(r[3]) : "r"(addr));
}
__device__ __forceinline__ void mma16816(float* d, const uint32_t* a, const uint32_t* b) {
    asm volatile("mma.sync.aligned.m16n8k16.row.col.f32.f16.f16.f32 "
                 "{%0,%1,%2,%3}, {%4,%5,%6,%7}, {%8,%9}, {%0,%1,%2,%3};"
                 : "+f"(d[0]), "+f"(d[1]), "+f"(d[2]), "+f"(d[3])
                 : "r"(a[0]), "r"(a[1]), "r"(a[2]), "r"(a[3]), "r"(b[0]), "r"(b[1]));
}
__device__ __forceinline__ void bulk_ld(uint32_t dst, const void* src, uint32_t mb) {
    asm volatile("cp.async.bulk.shared::cta.global.mbarrier::complete_tx::bytes "
                 "[%0], [%1], 128, [%2];"
                 :: "r"(dst), "l"(src), "r"(mb) : "memory");
}
__device__ __forceinline__ void mbar_wait(uint32_t mb, uint32_t parity) {
    uint32_t done;
    asm volatile(
        "{\n\t.reg .pred p;\n\t"
        "mbarrier.try_wait.parity.acquire.cta.shared::cta.b64 p, [%1], %2;\n\t"
        "selp.b32 %0, 1, 0, p;\n\t}"
        : "=r"(done) : "r"(mb), "r"(parity) : "memory");
    if (!done) {
        asm volatile(
            "{\n\t.reg .pred P1;\n\t"
            "WL_%=:\n\t"
            "mbarrier.try_wait.parity.acquire.cta.shared::cta.b64 P1, [%0], %1, 0x989680;\n\t"
            "@P1 bra.uni WD_%=;\n\t"
            "bra.uni WL_%=;\n\t"
            "WD_%=:\n\t}"
            :: "r"(mb), "r"(parity) : "memory");
    }
}

// ---------------------------------------------------------------------------
// Kernel 2: fp16 mma.sync implicit conv, 256 threads, 2 CTAs/SM.
// CTA strip: 12 input rows x 64 cols (10 x 56 valid outputs), w0 = 56*bx
// (multiple of 8 so the baked octet swizzle matches row&7). A rows staged by
// cp.async.bulk (one 128B linear copy per position) in 2 mbarrier phases.
// ---------------------------------------------------------------------------
__global__ __launch_bounds__(256, 2)
void conv_mma_kernel(const float* __restrict__ bias,
                     float* __restrict__ out) {
    extern __shared__ char smem[];
    const uint32_t sb  = smem_u32(smem);
    const int tid  = threadIdx.x;
    const int wid  = tid >> 5;
    const int lane = tid & 31;

    const int w0 = blockIdx.x * 56;
    const int h0 = blockIdx.y * 10;
    const int n  = blockIdx.z;

    if (tid < 64) {
        *(float*)(smem + ALPHA_OFF + tid * 4) = g_alpha[tid];
        *(float*)(smem + BIAS_OFF  + tid * 4) = __ldg(&bias[tid]);
    }
    if (tid == 0) {
        asm volatile("mbarrier.init.shared.b64 [%0], 1;" :: "r"(sb + MB_OFF)     : "memory");
        asm volatile("mbarrier.init.shared.b64 [%0], 1;" :: "r"(sb + MB_OFF + 8) : "memory");
    }
    // zero OOB-h rows (8 x 16B each)
    for (int p = tid; p < 768; p += 256) {
        int h = h0 + (p >> 6) - 1;
        if ((unsigned)h >= HH) {
            uint4* d = (uint4*)(smem + A_OFF + (p + 1) * 128);
            #pragma unroll
            for (int u = 0; u < 8; u++) d[u] = make_uint4(0, 0, 0, 0);
        }
    }
    // zero guard rows 0 and 769
    if (tid < 16) {
        int off = (tid < 8) ? tid * 16 : (769 * 128 + (tid - 8) * 16);
        *(uint4*)(smem + A_OFF + off) = make_uint4(0, 0, 0, 0);
    }
    __syncthreads();

    if (tid == 0) {
        int n1 = 0, n2 = 0;
        #pragma unroll
        for (int r = 0; r < 12; r++) {
            int h = h0 + r - 1;
            if ((unsigned)h < HH) { if (r < 7) n1 += 64; else n2 += 64; }
        }
        asm volatile("mbarrier.arrive.expect_tx.shared.b64 _, [%0], %1;"
                     :: "r"(sb + MB_OFF),     "r"(n1 * 128) : "memory");
        asm volatile("mbarrier.arrive.expect_tx.shared.b64 _, [%0], %1;"
                     :: "r"(sb + MB_OFF + 8), "r"(n2 * 128) : "memory");
    }
    __syncthreads();

    // issue bulk copies: one 128B row per in-bounds position
    {
        const __half* xb = g_xh + (size_t)n * HH * WPAD * 64;
        for (int p = tid; p < 768; p += 256) {
            int r = p >> 6, c = p & 63;
            int h = h0 + r - 1;
            if ((unsigned)h < HH) {
                const void* src = xb + ((size_t)h * WPAD + (w0 + c)) * 64;
                uint32_t mb = sb + MB_OFF + ((p < 448) ? 0 : 8);
                bulk_ld(sb + A_OFF + (uint32_t)(p + 1) * 128, src, mb);
            }
        }
    }

    // ---- compute
    const int wm  = wid & 3;         // 0..3 (M slice, m32)
    const int wn  = wid >> 2;        // 0..1 (N slice, n32)
    const int n0g = wn * 4;

    const int a_row = lane & 15;
    const int a_uo  = lane >> 4;

    const float* al = (const float*)(smem + ALPHA_OFF);
    const float* bi = (const float*)(smem + BIAS_OFF);

    #pragma unroll 1
    for (int t = 0; t < 5; t++) {
        if (t == 0) mbar_wait(sb + MB_OFF, 0);
        if (t == 2) mbar_wait(sb + MB_OFF + 8, 0);

        float acc[2][4][4];
        #pragma unroll
        for (int mc = 0; mc < 2; mc++)
            #pragma unroll
            for (int nc = 0; nc < 4; nc++)
                #pragma unroll
                for (int q = 0; q < 4; q++) acc[mc][nc][q] = 0.f;

        const int pt = 64 + t * 128 + wm * 32;

        #pragma unroll 1
        for (int tap = 0; tap < 9; tap++) {
            const int shift = (tap / 3) * 64 + (tap % 3) - 65;
            const uint2* wf = g_wfrag + (size_t)(tap * 8 + n0g) * 128 + lane;

            #pragma unroll
            for (int kc = 0; kc < 4; kc++) {
                uint2 bfr[4];
                #pragma unroll
                for (int nc = 0; nc < 4; nc++)
                    bfr[nc] = __ldg(wf + (nc * 4 + kc) * 32);

                #pragma unroll
                for (int mc = 0; mc < 2; mc++) {
                    int row = pt + mc * 16 + 1 + shift + a_row;
                    int u   = kc * 2 + a_uo;
                    uint32_t addr = sb + A_OFF + (uint32_t)(row * 128)
                                  + (uint32_t)((u ^ (row & 7)) << 4);
                    uint32_t afr[4];
                    ldsm_x4(afr, addr);
                    #pragma unroll
                    for (int nc = 0; nc < 4; nc++)
                        mma16816(acc[mc][nc], afr, (const uint32_t*)&bfr[nc]);
                }
            }
        }

        // ---- epilogue tile t: alpha*d + bias (valid cols c in 1..56)
        #pragma unroll
        for (int mc = 0; mc < 2; mc++) {
            #pragma unroll
            for (int rr = 0; rr < 2; rr++) {
                const int p = pt + mc * 16 + rr * 8 + (lane >> 2);
                const int c = p & 63, r = p >> 6;
                const int h = h0 + r - 1, w = w0 + c - 1;
                if (c >= 1 && c <= 56 && h < HH) {
                    float* ob = out + (((size_t)n * COUT) * HH + h) * WW + w;
                    #pragma unroll
                    for (int nc = 0; nc < 4; nc++) {
                        const int co = wn * 32 + nc * 8 + 2 * (lane & 3);
                        float v0 = acc[mc][nc][rr * 2 + 0] * al[co]     + bi[co];
                        float v1 = acc[mc][nc][rr * 2 + 1] * al[co + 1] + bi[co + 1];
                        ob[(size_t)co       * HH * WW] = v0;
                        ob[(size_t)(co + 1) * HH * WW] = v1;
                    }
                }
            }
        }
    }
}

// ---------------------------------------------------------------------------
extern "C" void kernel_launch(void* const* d_in, const int* in_sizes, int n_in,
                              void* d_out, int out_size) {
    const float* x      = (const float*)d_in[0];
    const float* weight = (const float*)d_in[1];
    const float* bias   = (const float*)d_in[2];
    float* out          = (float*)d_out;

    cudaFuncSetAttribute(conv_mma_kernel,
                         cudaFuncAttributeMaxDynamicSharedMemorySize, SMEM_TOTAL);

    ternarize_kernel<<<COUT, 256>>>(weight);
    pack_wfrag_kernel<<<36, 256>>>();
    transform_kernel<<<dim3(HH, NB), 256>>>(x);
    dim3 grid(4, 23, NB);   // 4 W-strips (56 wide), 23 H-strips (10 tall), N=16
    conv_mma_kernel<<<grid, 256, SMEM_TOTAL>>>(bias, out);
}